// round 5
// baseline (speedup 1.0000x reference)
#include <cuda_runtime.h>
#include <cstdint>

#define BB 8
#define MM 32
#define NCLS 80
#define N0 25600
#define N1 6400
#define N2 1600
#define NTOT 33600
#define TOPKK 10
#define DEC_BLK 132          // ceil(33600/256) decode blocks per image
#define SP_BLK 128           // softplus blocks per image
#define S0 512000            // 80*25600/4 float4 per image (p0 cls)
#define S1 128000            // 80*6400/4
#define S2 32000             // 80*1600/4
#define SP_TOT 672000        // S0+S1+S2
#define FG_MAX 2560          // <= 256 GTs * TOPK
#define FG_BLK 10            // FG_MAX / 256

// ---------------- scratch ----------------
__device__ float4 g_pb[BB * NTOT];                 // decoded pred boxes (image units)
__device__ unsigned long long g_best[BB * NTOT];   // (score_bits<<32 | (0xFFFFFFFF - m))
__device__ double g_sp_part[BB * SP_BLK];          // softplus block partials
__device__ int g_fglist[FG_MAX];                   // compacted fg anchor indices (b*NTOT+n)
__device__ int g_fgtot;
__device__ int g_fgcnt[BB];
__device__ float g_box[BB], g_dfl[BB], g_clspos[BB];
__device__ unsigned int g_done;

// ---------------- helpers ----------------
__device__ __forceinline__ float ciou_f(float b1x1, float b1y1, float b1x2, float b1y2,
                                        float b2x1, float b2y1, float b2x2, float b2y2) {
    const float eps = 1e-7f;
    float w1 = b1x2 - b1x1, h1 = b1y2 - b1y1;
    float w2 = b2x2 - b2x1, h2 = b2y2 - b2y1;
    float iw = fminf(b1x2, b2x2) - fmaxf(b1x1, b2x1);
    float ih = fminf(b1y2, b2y2) - fmaxf(b1y1, b2y1);
    float inter = fmaxf(iw, 0.f) * fmaxf(ih, 0.f);
    float uni = w1 * h1 + w2 * h2 - inter + eps;
    float iou = inter / uni;
    float cw = fmaxf(b1x2, b2x2) - fminf(b1x1, b2x1);
    float ch = fmaxf(b1y2, b2y2) - fminf(b1y1, b2y1);
    float c2 = cw * cw + ch * ch + eps;
    float dx = b2x1 + b2x2 - b1x1 - b1x2;
    float dy = b2y1 + b2y2 - b1y1 - b1y2;
    float rho2 = (dx * dx + dy * dy) * 0.25f;
    float dat = atanf(w2 / (h2 + eps)) - atanf(w1 / (h1 + eps));
    float v = 0.4052847345693511f * dat * dat;
    float alpha = v / (v - iou + (1.f + eps));
    return iou - (rho2 / c2 + v * alpha);
}

__device__ __forceinline__ unsigned long long umax64(unsigned long long a, unsigned long long b) {
    return a > b ? a : b;
}

__device__ __forceinline__ unsigned long long warp_max64(unsigned long long v) {
#pragma unroll
    for (int d = 16; d > 0; d >>= 1)
        v = umax64(v, __shfl_down_sync(0xffffffffu, v, d));
    return v;
}

// ================= k_decode: one thread per anchor =================
__global__ void __launch_bounds__(256) k_decode(
        const float* __restrict__ p0, const float* __restrict__ p1,
        const float* __restrict__ p2, const float* __restrict__ strides) {
    int b = blockIdx.y;
    int tid = threadIdx.x;
    int n = blockIdx.x * 256 + tid;

    if (blockIdx.x == 0 && tid == 0) {
        g_fgcnt[b] = 0; g_box[b] = 0.f; g_dfl[b] = 0.f; g_clspos[b] = 0.f;
        if (b == 0) { g_done = 0u; g_fgtot = 0; }
    }
    if (n >= NTOT) return;

    const float* p; int HW, q; float st, ax, ay;
    if (n < N0) {
        p = p0; HW = N0; q = n; st = strides[0];
        int qy = q / 160; ax = (float)(q - qy * 160) + 0.5f; ay = (float)qy + 0.5f;
    } else if (n < N0 + N1) {
        p = p1; HW = N1; q = n - N0; st = strides[1];
        int qy = q / 80; ax = (float)(q - qy * 80) + 0.5f; ay = (float)qy + 0.5f;
    } else {
        p = p2; HW = N2; q = n - (N0 + N1); st = strides[2];
        int qy = q / 40; ax = (float)(q - qy * 40) + 0.5f; ay = (float)qy + 0.5f;
    }

    const float* pb = p + (size_t)b * 144 * HW + q;
    float dist[4];
#pragma unroll
    for (int k = 0; k < 4; k++) {
        float x[16];
#pragma unroll
        for (int r = 0; r < 16; r++) x[r] = pb[(size_t)(k * 16 + r) * HW];
        float se = 0.f, sw = 0.f;
#pragma unroll
        for (int r = 0; r < 16; r++) {
            float e = __expf(x[r]);
            se += e; sw = fmaf(e, (float)r, sw);
        }
        dist[k] = sw / se;
    }
    float4 out;
    out.x = (ax - dist[0]) * st;
    out.y = (ay - dist[1]) * st;
    out.z = (ax + dist[2]) * st;
    out.w = (ay + dist[3]) * st;
    int idx = b * NTOT + n;
    g_pb[idx] = out;
    g_best[idx] = 0xFFFFFFFFull;   // sentinel: score 0, m = 0
}

// ================= k_softplus: independent 86MB stream (side branch) =================
__global__ void __launch_bounds__(256) k_softplus(
        const float* __restrict__ p0, const float* __restrict__ p1,
        const float* __restrict__ p2) {
    int b = blockIdx.y;
    int tid = threadIdx.x;
    const float4* f40 = (const float4*)(p0 + ((size_t)b * 144 + 64) * N0);
    const float4* f41 = (const float4*)(p1 + ((size_t)b * 144 + 64) * N1);
    const float4* f42 = (const float4*)(p2 + ((size_t)b * 144 + 64) * N2);
    float acc = 0.f;
    float P0 = 1.f, P1 = 1.f, P2 = 1.f, P3 = 1.f;
    int cnt = 0;
    for (int i = blockIdx.x * 256 + tid; i < SP_TOT; i += SP_BLK * 256) {
        float4 v;
        if (i < S0)           v = f40[i];
        else if (i < S0 + S1) v = f41[i - S0];
        else                  v = f42[i - S0 - S1];
        acc += fmaxf(v.x, 0.f) + fmaxf(v.y, 0.f) + fmaxf(v.z, 0.f) + fmaxf(v.w, 0.f);
        P0 *= 1.f + __expf(-fabsf(v.x));
        P1 *= 1.f + __expf(-fabsf(v.y));
        P2 *= 1.f + __expf(-fabsf(v.z));
        P3 *= 1.f + __expf(-fabsf(v.w));
        if ((++cnt & 7) == 0) {   // flush every 32 terms (each <= 2)
            acc += __logf((P0 * P1) * (P2 * P3));
            P0 = P1 = P2 = P3 = 1.f;
        }
    }
    acc += __logf((P0 * P1) * (P2 * P3));

    __shared__ double sred[256];
    sred[tid] = (double)acc;
    __syncthreads();
    for (int s = 128; s > 0; s >>= 1) {
        if (tid < s) sred[tid] += sred[tid + s];
        __syncthreads();
    }
    if (tid == 0) g_sp_part[b * SP_BLK + blockIdx.x] = sred[0];
}

// ================= k_assign: one block per (b,m), rect scan + fg compaction =====
__global__ void __launch_bounds__(256) k_assign(
        const float* __restrict__ p0, const float* __restrict__ p1,
        const float* __restrict__ p2,
        const float* __restrict__ gt_boxes, const int* __restrict__ gt_labels,
        const float* __restrict__ strides) {
    __shared__ unsigned long long sh_keys[256 * TOPKK];
    __shared__ unsigned long long sh_w[8];
    __shared__ unsigned long long sh_best;
    __shared__ float sh_fw[8];
    __shared__ float sh_cmax;

    int bm = blockIdx.x;
    int b = bm >> 5, m = bm & 31;
    int tid = threadIdx.x;
    int wid = tid >> 5, lid = tid & 31;

    float gx1 = gt_boxes[(b * MM + m) * 4 + 0];
    float gy1 = gt_boxes[(b * MM + m) * 4 + 1];
    float gx2 = gt_boxes[(b * MM + m) * 4 + 2];
    float gy2 = gt_boxes[(b * MM + m) * 4 + 3];
    int label = gt_labels[b * MM + m];

    float tv[TOPKK]; int tn[TOPKK];
#pragma unroll
    for (int jj = 0; jj < TOPKK; jj++) { tv[jj] = 0.f; tn[jj] = 0x7FFFFFFF; }
    float cmax = 0.f;

#pragma unroll
    for (int lvl = 0; lvl < 3; lvl++) {
        const float* p; int HW, W, noff; float st;
        if (lvl == 0)      { p = p0; HW = N0; W = 160; noff = 0;       st = strides[0]; }
        else if (lvl == 1) { p = p1; HW = N1; W = 80;  noff = N0;      st = strides[1]; }
        else               { p = p2; HW = N2; W = 40;  noff = N0 + N1; st = strides[2]; }

        float inv = 1.f / st;
        int x0 = max(0, (int)(gx1 * inv - 0.5f) - 1);
        int x1 = min(W - 1, (int)(gx2 * inv - 0.5f) + 1);
        int y0 = max(0, (int)(gy1 * inv - 0.5f) - 1);
        int y1 = min(W - 1, (int)(gy2 * inv - 0.5f) + 1);
        int rw = x1 - x0 + 1, rh = y1 - y0 + 1;
        if (rw <= 0 || rh <= 0) continue;
        int tot = rw * rh;
        const float* pcl = p + ((size_t)b * 144 + 64 + label) * HW;

        for (int i = tid; i < tot; i += 256) {
            int qx = x0 + i % rw;
            int qy = y0 + i / rw;
            float ax = ((float)qx + 0.5f) * st;
            float ay = ((float)qy + 0.5f) * st;
            if (ax < gx1 || ax > gx2 || ay < gy1 || ay > gy2) continue;
            int q = qy * W + qx;
            int n = noff + q;
            float4 pbv = g_pb[b * NTOT + n];
            float iou = fmaxf(ciou_f(pbv.x, pbv.y, pbv.z, pbv.w, gx1, gy1, gx2, gy2), 0.f);
            float pcv = pcl[q];
            float ps = 1.f / (1.f + __expf(-pcv));
            float i2 = iou * iou;
            float align = ps * (i2 * i2 * i2);
            cmax = fmaxf(cmax, align);
            if (iou > 0.1f && align > 0.f &&
                ((align > tv[TOPKK - 1]) ||
                 (align == tv[TOPKK - 1] && n < tn[TOPKK - 1]))) {
                float cv = align; int cn = n;
#pragma unroll
                for (int jj = 0; jj < TOPKK; jj++) {
                    bool bt = (cv > tv[jj]) || (cv == tv[jj] && cn < tn[jj]);
                    float nv = bt ? cv : tv[jj];  int nn = bt ? cn : tn[jj];
                    cv = bt ? tv[jj] : cv;        cn = bt ? tn[jj] : cn;
                    tv[jj] = nv;                  tn[jj] = nn;
                }
            }
        }
    }

    // column max (raw align, pre-mask) via warp shuffles
#pragma unroll
    for (int d = 16; d > 0; d >>= 1)
        cmax = fmaxf(cmax, __shfl_down_sync(0xffffffffu, cmax, d));
    if (lid == 0) sh_fw[wid] = cmax;
    __syncthreads();
    if (tid == 0) {
        float c = sh_fw[0];
#pragma unroll
        for (int w = 1; w < 8; w++) c = fmaxf(c, sh_fw[w]);
        sh_cmax = c;
    }

#pragma unroll
    for (int jj = 0; jj < TOPKK; jj++) {
        unsigned long long key = 0ull;
        if (tv[jj] > 0.f)
            key = ((unsigned long long)__float_as_uint(tv[jj]) << 32) |
                  (unsigned long long)(0xFFFFFFFFu - (unsigned)tn[jj]);
        sh_keys[tid * TOPKK + jj] = key;
    }
    __syncthreads();
    float colmax = sh_cmax;

    for (int iter = 0; iter < TOPKK; iter++) {
        unsigned long long loc = 0ull;
#pragma unroll
        for (int jj = 0; jj < TOPKK; jj++)
            loc = umax64(loc, sh_keys[tid + jj * 256]);
        loc = warp_max64(loc);
        if (lid == 0) sh_w[wid] = loc;
        __syncthreads();
        if (tid == 0) {
            unsigned long long v = sh_w[0];
#pragma unroll
            for (int w = 1; w < 8; w++) v = umax64(v, sh_w[w]);
            sh_best = v;
        }
        __syncthreads();
        unsigned long long bestk = sh_best;
        if (bestk == 0ull) break;
#pragma unroll
        for (int jj = 0; jj < TOPKK; jj++)
            if (sh_keys[tid * TOPKK + jj] == bestk) sh_keys[tid * TOPKK + jj] = 0ull;
        if (tid == 0) {
            float val = __uint_as_float((unsigned)(bestk >> 32));
            int n = (int)(0xFFFFFFFFu - (unsigned)(bestk & 0xFFFFFFFFull));
            float norm = val / (colmax + 1e-9f);
            unsigned long long okey =
                ((unsigned long long)__float_as_uint(norm) << 32) |
                (unsigned long long)(0xFFFFFFFFu - (unsigned)m);
            int gidx = b * NTOT + n;
            unsigned long long old = atomicMax(&g_best[gidx], okey);
            // exactly one writer per anchor sees the sentinel -> compaction for free
            if (old == 0xFFFFFFFFull) {
                atomicAdd(&g_fgcnt[b], 1);
                int pos = atomicAdd(&g_fgtot, 1);
                g_fglist[pos] = gidx;
            }
        }
        __syncthreads();
    }
}

// ============ k_fg: fg losses over compacted list + last-block final combine ========
__global__ void __launch_bounds__(256) k_fg(
        const float* __restrict__ p0, const float* __restrict__ p1,
        const float* __restrict__ p2,
        const float* __restrict__ gt_boxes, const int* __restrict__ gt_labels,
        const float* __restrict__ strides, float* __restrict__ out) {
    int tid = threadIdx.x;
    int i = blockIdx.x * 256 + tid;

    if (i < g_fgtot) {
        int idx = g_fglist[i];
        unsigned long long key = g_best[idx];
        float score = __uint_as_float((unsigned)(key >> 32));
        int b = idx / NTOT, n = idx % NTOT;
        int m = (int)(0xFFFFFFFFu - (unsigned)(key & 0xFFFFFFFFull));

        float gx1 = gt_boxes[(b * MM + m) * 4 + 0];
        float gy1 = gt_boxes[(b * MM + m) * 4 + 1];
        float gx2 = gt_boxes[(b * MM + m) * 4 + 2];
        float gy2 = gt_boxes[(b * MM + m) * 4 + 3];
        int label = gt_labels[b * MM + m];

        const float* p; int HW, W, q; float st;
        if (n < N0)           { p = p0; HW = N0; W = 160; q = n;             st = strides[0]; }
        else if (n < N0 + N1) { p = p1; HW = N1; W = 80;  q = n - N0;        st = strides[1]; }
        else                  { p = p2; HW = N2; W = 40;  q = n - (N0 + N1); st = strides[2]; }
        float ax = (float)(q % W) + 0.5f;
        float ay = (float)(q / W) + 0.5f;

        float4 pbv = g_pb[idx];
        float boxl = 1.f - ciou_f(pbv.x, pbv.y, pbv.z, pbv.w, gx1, gy1, gx2, gy2);

        float t[4];
        t[0] = ax - gx1 / st;
        t[1] = ay - gy1 / st;
        t[2] = gx2 / st - ax;
        t[3] = gy2 / st - ay;

        float dfl = 0.f;
#pragma unroll
        for (int k = 0; k < 4; k++) {
            float tt = fminf(fmaxf(t[k], 0.f), 14.99f);
            int li = (int)floorf(tt);
            int ri = min(li + 1, 15);
            float wl = (float)ri - tt, wr = tt - (float)li;
            const float* base = p + ((size_t)b * 144 + k * 16) * HW + q;
            float x[16];
#pragma unroll
            for (int r = 0; r < 16; r++) x[r] = base[(size_t)r * HW];
            float mx = x[0];
#pragma unroll
            for (int r = 1; r < 16; r++) mx = fmaxf(mx, x[r]);
            float se = 0.f;
#pragma unroll
            for (int r = 0; r < 16; r++) se += expf(x[r] - mx);
            float lse = mx + logf(se);
            dfl += wl * (lse - x[li]) + wr * (lse - x[ri]);
        }

        float pcv = p[((size_t)b * 144 + 64 + label) * HW + q];

        atomicAdd(&g_box[b], boxl);
        atomicAdd(&g_dfl[b], dfl);
        atomicAdd(&g_clspos[b], pcv * score);
    }

    // ---- completion detection: last block computes the final scalar ----
    __shared__ bool s_last;
    __syncthreads();
    if (tid == 0) {
        __threadfence();
        unsigned v = atomicAdd(&g_done, 1u);
        s_last = (v == (unsigned)(gridDim.x - 1));
    }
    __syncthreads();
    if (!s_last) return;

    int w = tid >> 5, l = tid & 31;
    __shared__ double s8[8];
    if (w < 8) {
        double sp = 0.0;
        for (int j = l; j < SP_BLK; j += 32) sp += g_sp_part[w * SP_BLK + j];
#pragma unroll
        for (int d = 16; d > 0; d >>= 1) sp += __shfl_down_sync(0xffffffffu, sp, d);
        if (l == 0) {
            int cnt = g_fgcnt[w];
            double has = cnt > 0 ? 1.0 : 0.0;
            double nf = cnt > 0 ? (double)cnt : 1.0;
            double bl = (double)g_box[w] / nf;
            double dl = (double)g_dfl[w] / (nf * 4.0);
            double cl = (sp - (double)g_clspos[w]) / (double)NTOT;
            s8[w] = (7.5 * bl + 0.5 * cl + 1.5 * dl) * has;
        }
    }
    __syncthreads();
    if (tid == 0) {
        double total = 0.0;
#pragma unroll
        for (int b = 0; b < BB; b++) total += s8[b];
        out[0] = (float)total;
    }
}

// ---------------- launch: fork softplus onto a side branch ----------------
extern "C" void kernel_launch(void* const* d_in, const int* in_sizes, int n_in,
                              void* d_out, int out_size) {
    const float* p0 = (const float*)d_in[0];
    const float* p1 = (const float*)d_in[1];
    const float* p2 = (const float*)d_in[2];
    const float* gtb = (const float*)d_in[3];
    const int* gtl = (const int*)d_in[4];
    const float* strides = (const float*)d_in[5];
    float* out = (float*)d_out;

    static cudaStream_t s_side = nullptr;
    static cudaEvent_t ev_fork = nullptr, ev_join = nullptr;
    if (s_side == nullptr) {
        cudaStreamCreateWithFlags(&s_side, cudaStreamNonBlocking);
        cudaEventCreateWithFlags(&ev_fork, cudaEventDisableTiming);
        cudaEventCreateWithFlags(&ev_join, cudaEventDisableTiming);
    }

    // fork: side branch runs the independent 86MB softplus stream
    cudaEventRecord(ev_fork, 0);
    cudaStreamWaitEvent(s_side, ev_fork, 0);
    k_softplus<<<dim3(SP_BLK, BB), 256, 0, s_side>>>(p0, p1, p2);
    cudaEventRecord(ev_join, s_side);

    // main branch: decode -> assign
    k_decode<<<dim3(DEC_BLK, BB), 256>>>(p0, p1, p2, strides);
    k_assign<<<BB * MM, 256>>>(p0, p1, p2, gtb, gtl, strides);

    // join before fg (fg's last block consumes g_sp_part)
    cudaStreamWaitEvent(0, ev_join, 0);
    k_fg<<<FG_BLK, 256>>>(p0, p1, p2, gtb, gtl, strides, out);
}

// round 7
// speedup vs baseline: 1.1189x; 1.1189x over previous
#include <cuda_runtime.h>
#include <cstdint>

#define BB 8
#define MM 32
#define NCLS 80
#define N0 25600
#define N1 6400
#define N2 1600
#define NTOT 33600
#define TOPKK 10
#define DEC_BLK 132          // ceil(33600/256) decode blocks per image
#define SP_BLK 128           // softplus blocks per image
#define S0 512000            // 80*25600/4 float4 per image (p0 cls)
#define S1 128000            // 80*6400/4
#define S2 32000             // 80*1600/4
#define SP_TOT 672000        // S0+S1+S2
#define FG_MAX 2560          // <= 256 GTs * TOPK
#define FG_BLK 320           // 2560 warps / 8 warps-per-block = 320 blocks

// ---------------- scratch ----------------
__device__ float4 g_pb[BB * NTOT];                 // decoded pred boxes (image units)
__device__ unsigned long long g_best[BB * NTOT];   // (score_bits<<32 | (0xFFFFFFFF - m))
__device__ double g_sp_part[BB * SP_BLK];          // softplus block partials
__device__ int g_fglist[FG_MAX];                   // compacted fg anchor indices (b*NTOT+n)
__device__ int g_fgtot;
__device__ int g_fgcnt[BB];
__device__ float g_box[BB], g_dfl[BB], g_clspos[BB];
__device__ unsigned int g_done;

// ---------------- helpers ----------------
__device__ __forceinline__ float ciou_f(float b1x1, float b1y1, float b1x2, float b1y2,
                                        float b2x1, float b2y1, float b2x2, float b2y2) {
    const float eps = 1e-7f;
    float w1 = b1x2 - b1x1, h1 = b1y2 - b1y1;
    float w2 = b2x2 - b2x1, h2 = b2y2 - b2y1;
    float iw = fminf(b1x2, b2x2) - fmaxf(b1x1, b2x1);
    float ih = fminf(b1y2, b2y2) - fmaxf(b1y1, b2y1);
    float inter = fmaxf(iw, 0.f) * fmaxf(ih, 0.f);
    float uni = w1 * h1 + w2 * h2 - inter + eps;
    float iou = inter / uni;
    float cw = fmaxf(b1x2, b2x2) - fminf(b1x1, b2x1);
    float ch = fmaxf(b1y2, b2y2) - fminf(b1y1, b2y1);
    float c2 = cw * cw + ch * ch + eps;
    float dx = b2x1 + b2x2 - b1x1 - b1x2;
    float dy = b2y1 + b2y2 - b1y1 - b1y2;
    float rho2 = (dx * dx + dy * dy) * 0.25f;
    float dat = atanf(w2 / (h2 + eps)) - atanf(w1 / (h1 + eps));
    float v = 0.4052847345693511f * dat * dat;
    float alpha = v / (v - iou + (1.f + eps));
    return iou - (rho2 / c2 + v * alpha);
}

__device__ __forceinline__ unsigned long long umax64(unsigned long long a, unsigned long long b) {
    return a > b ? a : b;
}

__device__ __forceinline__ unsigned long long warp_max64(unsigned long long v) {
#pragma unroll
    for (int d = 16; d > 0; d >>= 1)
        v = umax64(v, __shfl_down_sync(0xffffffffu, v, d));
    return v;
}

// ================= k_decode: one thread per anchor =================
__global__ void __launch_bounds__(256) k_decode(
        const float* __restrict__ p0, const float* __restrict__ p1,
        const float* __restrict__ p2, const float* __restrict__ strides) {
    int b = blockIdx.y;
    int tid = threadIdx.x;
    int n = blockIdx.x * 256 + tid;

    if (blockIdx.x == 0 && tid == 0) {
        g_fgcnt[b] = 0; g_box[b] = 0.f; g_dfl[b] = 0.f; g_clspos[b] = 0.f;
        if (b == 0) { g_done = 0u; g_fgtot = 0; }
    }
    if (n >= NTOT) return;

    const float* p; int HW, q; float st, ax, ay;
    if (n < N0) {
        p = p0; HW = N0; q = n; st = strides[0];
        int qy = q / 160; ax = (float)(q - qy * 160) + 0.5f; ay = (float)qy + 0.5f;
    } else if (n < N0 + N1) {
        p = p1; HW = N1; q = n - N0; st = strides[1];
        int qy = q / 80; ax = (float)(q - qy * 80) + 0.5f; ay = (float)qy + 0.5f;
    } else {
        p = p2; HW = N2; q = n - (N0 + N1); st = strides[2];
        int qy = q / 40; ax = (float)(q - qy * 40) + 0.5f; ay = (float)qy + 0.5f;
    }

    const float* pb = p + (size_t)b * 144 * HW + q;
    float dist[4];
#pragma unroll
    for (int k = 0; k < 4; k++) {
        float x[16];
#pragma unroll
        for (int r = 0; r < 16; r++) x[r] = pb[(size_t)(k * 16 + r) * HW];
        float se = 0.f, sw = 0.f;
#pragma unroll
        for (int r = 0; r < 16; r++) {
            float e = __expf(x[r]);
            se += e; sw = fmaf(e, (float)r, sw);
        }
        dist[k] = sw / se;
    }
    float4 out;
    out.x = (ax - dist[0]) * st;
    out.y = (ay - dist[1]) * st;
    out.z = (ax + dist[2]) * st;
    out.w = (ay + dist[3]) * st;
    int idx = b * NTOT + n;
    g_pb[idx] = out;
    g_best[idx] = 0xFFFFFFFFull;   // sentinel: score 0, m = 0
}

// ================= k_softplus: independent 86MB stream (side branch) =================
__global__ void __launch_bounds__(256) k_softplus(
        const float* __restrict__ p0, const float* __restrict__ p1,
        const float* __restrict__ p2) {
    int b = blockIdx.y;
    int tid = threadIdx.x;
    const float4* f40 = (const float4*)(p0 + ((size_t)b * 144 + 64) * N0);
    const float4* f41 = (const float4*)(p1 + ((size_t)b * 144 + 64) * N1);
    const float4* f42 = (const float4*)(p2 + ((size_t)b * 144 + 64) * N2);
    float acc = 0.f;
    float P0 = 1.f, P1 = 1.f, P2 = 1.f, P3 = 1.f;
    int cnt = 0;
    for (int i = blockIdx.x * 256 + tid; i < SP_TOT; i += SP_BLK * 256) {
        float4 v;
        if (i < S0)           v = f40[i];
        else if (i < S0 + S1) v = f41[i - S0];
        else                  v = f42[i - S0 - S1];
        acc += fmaxf(v.x, 0.f) + fmaxf(v.y, 0.f) + fmaxf(v.z, 0.f) + fmaxf(v.w, 0.f);
        P0 *= 1.f + __expf(-fabsf(v.x));
        P1 *= 1.f + __expf(-fabsf(v.y));
        P2 *= 1.f + __expf(-fabsf(v.z));
        P3 *= 1.f + __expf(-fabsf(v.w));
        if ((++cnt & 7) == 0) {   // flush every 32 terms (each <= 2)
            acc += __logf((P0 * P1) * (P2 * P3));
            P0 = P1 = P2 = P3 = 1.f;
        }
    }
    acc += __logf((P0 * P1) * (P2 * P3));

    __shared__ double sred[256];
    sred[tid] = (double)acc;
    __syncthreads();
    for (int s = 128; s > 0; s >>= 1) {
        if (tid < s) sred[tid] += sred[tid + s];
        __syncthreads();
    }
    if (tid == 0) g_sp_part[b * SP_BLK + blockIdx.x] = sred[0];
}

// ================= k_assign: one block per (b,m), rect scan + fg compaction =====
__global__ void __launch_bounds__(256) k_assign(
        const float* __restrict__ p0, const float* __restrict__ p1,
        const float* __restrict__ p2,
        const float* __restrict__ gt_boxes, const int* __restrict__ gt_labels,
        const float* __restrict__ strides) {
    __shared__ unsigned long long sh_keys[256 * TOPKK];
    __shared__ unsigned long long sh_w[8];
    __shared__ unsigned long long sh_best;
    __shared__ float sh_fw[8];
    __shared__ float sh_cmax;

    int bm = blockIdx.x;
    int b = bm >> 5, m = bm & 31;
    int tid = threadIdx.x;
    int wid = tid >> 5, lid = tid & 31;

    float gx1 = gt_boxes[(b * MM + m) * 4 + 0];
    float gy1 = gt_boxes[(b * MM + m) * 4 + 1];
    float gx2 = gt_boxes[(b * MM + m) * 4 + 2];
    float gy2 = gt_boxes[(b * MM + m) * 4 + 3];
    int label = gt_labels[b * MM + m];

    float tv[TOPKK]; int tn[TOPKK];
#pragma unroll
    for (int jj = 0; jj < TOPKK; jj++) { tv[jj] = 0.f; tn[jj] = 0x7FFFFFFF; }
    float cmax = 0.f;

#pragma unroll
    for (int lvl = 0; lvl < 3; lvl++) {
        const float* p; int HW, W, noff; float st;
        if (lvl == 0)      { p = p0; HW = N0; W = 160; noff = 0;       st = strides[0]; }
        else if (lvl == 1) { p = p1; HW = N1; W = 80;  noff = N0;      st = strides[1]; }
        else               { p = p2; HW = N2; W = 40;  noff = N0 + N1; st = strides[2]; }

        float inv = 1.f / st;
        int x0 = max(0, (int)(gx1 * inv - 0.5f) - 1);
        int x1 = min(W - 1, (int)(gx2 * inv - 0.5f) + 1);
        int y0 = max(0, (int)(gy1 * inv - 0.5f) - 1);
        int y1 = min(W - 1, (int)(gy2 * inv - 0.5f) + 1);
        int rw = x1 - x0 + 1, rh = y1 - y0 + 1;
        if (rw <= 0 || rh <= 0) continue;
        int tot = rw * rh;
        const float* pcl = p + ((size_t)b * 144 + 64 + label) * HW;

        for (int i = tid; i < tot; i += 256) {
            int qx = x0 + i % rw;
            int qy = y0 + i / rw;
            float ax = ((float)qx + 0.5f) * st;
            float ay = ((float)qy + 0.5f) * st;
            if (ax < gx1 || ax > gx2 || ay < gy1 || ay > gy2) continue;
            int q = qy * W + qx;
            int n = noff + q;
            float4 pbv = g_pb[b * NTOT + n];
            float iou = fmaxf(ciou_f(pbv.x, pbv.y, pbv.z, pbv.w, gx1, gy1, gx2, gy2), 0.f);
            float pcv = pcl[q];
            float ps = 1.f / (1.f + __expf(-pcv));
            float i2 = iou * iou;
            float align = ps * (i2 * i2 * i2);
            cmax = fmaxf(cmax, align);
            if (iou > 0.1f && align > 0.f &&
                ((align > tv[TOPKK - 1]) ||
                 (align == tv[TOPKK - 1] && n < tn[TOPKK - 1]))) {
                float cv = align; int cn = n;
#pragma unroll
                for (int jj = 0; jj < TOPKK; jj++) {
                    bool bt = (cv > tv[jj]) || (cv == tv[jj] && cn < tn[jj]);
                    float nv = bt ? cv : tv[jj];  int nn = bt ? cn : tn[jj];
                    cv = bt ? tv[jj] : cv;        cn = bt ? tn[jj] : cn;
                    tv[jj] = nv;                  tn[jj] = nn;
                }
            }
        }
    }

    // column max (raw align, pre-mask) via warp shuffles
#pragma unroll
    for (int d = 16; d > 0; d >>= 1)
        cmax = fmaxf(cmax, __shfl_down_sync(0xffffffffu, cmax, d));
    if (lid == 0) sh_fw[wid] = cmax;
    __syncthreads();
    if (tid == 0) {
        float c = sh_fw[0];
#pragma unroll
        for (int w = 1; w < 8; w++) c = fmaxf(c, sh_fw[w]);
        sh_cmax = c;
    }

#pragma unroll
    for (int jj = 0; jj < TOPKK; jj++) {
        unsigned long long key = 0ull;
        if (tv[jj] > 0.f)
            key = ((unsigned long long)__float_as_uint(tv[jj]) << 32) |
                  (unsigned long long)(0xFFFFFFFFu - (unsigned)tn[jj]);
        sh_keys[tid * TOPKK + jj] = key;
    }
    __syncthreads();
    float colmax = sh_cmax;

    for (int iter = 0; iter < TOPKK; iter++) {
        unsigned long long loc = 0ull;
#pragma unroll
        for (int jj = 0; jj < TOPKK; jj++)
            loc = umax64(loc, sh_keys[tid + jj * 256]);
        loc = warp_max64(loc);
        if (lid == 0) sh_w[wid] = loc;
        __syncthreads();
        if (tid == 0) {
            unsigned long long v = sh_w[0];
#pragma unroll
            for (int w = 1; w < 8; w++) v = umax64(v, sh_w[w]);
            sh_best = v;
        }
        __syncthreads();
        unsigned long long bestk = sh_best;
        if (bestk == 0ull) break;
#pragma unroll
        for (int jj = 0; jj < TOPKK; jj++)
            if (sh_keys[tid * TOPKK + jj] == bestk) sh_keys[tid * TOPKK + jj] = 0ull;
        if (tid == 0) {
            float val = __uint_as_float((unsigned)(bestk >> 32));
            int n = (int)(0xFFFFFFFFu - (unsigned)(bestk & 0xFFFFFFFFull));
            float norm = val / (colmax + 1e-9f);
            unsigned long long okey =
                ((unsigned long long)__float_as_uint(norm) << 32) |
                (unsigned long long)(0xFFFFFFFFu - (unsigned)m);
            int gidx = b * NTOT + n;
            unsigned long long old = atomicMax(&g_best[gidx], okey);
            // exactly one writer per anchor sees the sentinel -> compaction for free
            if (old == 0xFFFFFFFFull) {
                atomicAdd(&g_fgcnt[b], 1);
                int pos = atomicAdd(&g_fgtot, 1);
                g_fglist[pos] = gidx;
            }
        }
        __syncthreads();
    }
}

// ============ k_fg: ONE WARP PER FG ANCHOR (lane-parallel DFL) + final combine ======
__global__ void __launch_bounds__(256) k_fg(
        const float* __restrict__ p0, const float* __restrict__ p1,
        const float* __restrict__ p2,
        const float* __restrict__ gt_boxes, const int* __restrict__ gt_labels,
        const float* __restrict__ strides, float* __restrict__ out) {
    int tid = threadIdx.x;
    int lane = tid & 31;
    int i = blockIdx.x * 8 + (tid >> 5);      // global warp id = fg index

    if (i < g_fgtot) {
        int idx = g_fglist[i];
        unsigned long long key = g_best[idx];
        float score = __uint_as_float((unsigned)(key >> 32));
        int b = idx / NTOT, n = idx % NTOT;
        int m = (int)(0xFFFFFFFFu - (unsigned)(key & 0xFFFFFFFFull));

        float gx1 = gt_boxes[(b * MM + m) * 4 + 0];
        float gy1 = gt_boxes[(b * MM + m) * 4 + 1];
        float gx2 = gt_boxes[(b * MM + m) * 4 + 2];
        float gy2 = gt_boxes[(b * MM + m) * 4 + 3];
        int label = gt_labels[b * MM + m];

        const float* p; int HW, W, q; float st;
        if (n < N0)           { p = p0; HW = N0; W = 160; q = n;             st = strides[0]; }
        else if (n < N0 + N1) { p = p1; HW = N1; W = 80;  q = n - N0;        st = strides[1]; }
        else                  { p = p2; HW = N2; W = 40;  q = n - (N0 + N1); st = strides[2]; }
        float ax = (float)(q % W) + 0.5f;
        float ay = (float)(q / W) + 0.5f;

        // lane-parallel load of the 64 dist channels: channel = lane, lane+32
        const float* base = p + (size_t)b * 144 * HW + q;
        float x0 = base[(size_t)lane * HW];          // channels 0-31  (sides 0,1)
        float x1 = base[(size_t)(lane + 32) * HW];   // channels 32-63 (sides 2,3)

        // per-side sum of exp via 16-lane segmented xor-reduction
        float e0 = __expf(x0), e1 = __expf(x1);
#pragma unroll
        for (int d = 1; d < 16; d <<= 1) {
            e0 += __shfl_xor_sync(0xffffffffu, e0, d);
            e1 += __shfl_xor_sync(0xffffffffu, e1, d);
        }
        float lse0 = __logf(__shfl_sync(0xffffffffu, e0, 0));
        float lse1 = __logf(__shfl_sync(0xffffffffu, e0, 16));
        float lse2 = __logf(__shfl_sync(0xffffffffu, e1, 0));
        float lse3 = __logf(__shfl_sync(0xffffffffu, e1, 16));

        // targets (identical on all lanes)
        float t0 = fminf(fmaxf(ax - gx1 / st, 0.f), 14.99f);
        float t1 = fminf(fmaxf(ay - gy1 / st, 0.f), 14.99f);
        float t2 = fminf(fmaxf(gx2 / st - ax, 0.f), 14.99f);
        float t3 = fminf(fmaxf(gy2 / st - ay, 0.f), 14.99f);
        int l0 = (int)t0, l1 = (int)t1, l2 = (int)t2, l3 = (int)t3;
        int r0 = min(l0 + 1, 15), r1 = min(l1 + 1, 15), r2 = min(l2 + 1, 15), r3 = min(l3 + 1, 15);

        float xl0 = __shfl_sync(0xffffffffu, x0, l0);
        float xr0 = __shfl_sync(0xffffffffu, x0, r0);
        float xl1 = __shfl_sync(0xffffffffu, x0, 16 + l1);
        float xr1 = __shfl_sync(0xffffffffu, x0, 16 + r1);
        float xl2 = __shfl_sync(0xffffffffu, x1, l2);
        float xr2 = __shfl_sync(0xffffffffu, x1, r2);
        float xl3 = __shfl_sync(0xffffffffu, x1, 16 + l3);
        float xr3 = __shfl_sync(0xffffffffu, x1, 16 + r3);

        if (lane == 0) {
            float dfl =
                ((float)r0 - t0) * (lse0 - xl0) + (t0 - (float)l0) * (lse0 - xr0) +
                ((float)r1 - t1) * (lse1 - xl1) + (t1 - (float)l1) * (lse1 - xr1) +
                ((float)r2 - t2) * (lse2 - xl2) + (t2 - (float)l2) * (lse2 - xr2) +
                ((float)r3 - t3) * (lse3 - xl3) + (t3 - (float)l3) * (lse3 - xr3);

            float4 pbv = g_pb[idx];
            float boxl = 1.f - ciou_f(pbv.x, pbv.y, pbv.z, pbv.w, gx1, gy1, gx2, gy2);
            float pcv = base[(size_t)(64 + label) * HW];

            atomicAdd(&g_box[b], boxl);
            atomicAdd(&g_dfl[b], dfl);
            atomicAdd(&g_clspos[b], pcv * score);
        }
    }

    // ---- completion detection: last block computes the final scalar ----
    __shared__ bool s_last;
    __syncthreads();
    if (tid == 0) {
        __threadfence();
        unsigned v = atomicAdd(&g_done, 1u);
        s_last = (v == (unsigned)(gridDim.x - 1));
    }
    __syncthreads();
    if (!s_last) return;

    int w = tid >> 5, l = tid & 31;
    __shared__ double s8[8];
    if (w < 8) {
        double sp = 0.0;
        for (int j = l; j < SP_BLK; j += 32) sp += g_sp_part[w * SP_BLK + j];
#pragma unroll
        for (int d = 16; d > 0; d >>= 1) sp += __shfl_down_sync(0xffffffffu, sp, d);
        if (l == 0) {
            int cnt = g_fgcnt[w];
            double has = cnt > 0 ? 1.0 : 0.0;
            double nf = cnt > 0 ? (double)cnt : 1.0;
            double bl = (double)g_box[w] / nf;
            double dl = (double)g_dfl[w] / (nf * 4.0);
            double cl = (sp - (double)g_clspos[w]) / (double)NTOT;
            s8[w] = (7.5 * bl + 0.5 * cl + 1.5 * dl) * has;
        }
    }
    __syncthreads();
    if (tid == 0) {
        double total = 0.0;
#pragma unroll
        for (int b = 0; b < BB; b++) total += s8[b];
        out[0] = (float)total;
    }
}

// ---------------- launch: fork softplus onto a side branch ----------------
extern "C" void kernel_launch(void* const* d_in, const int* in_sizes, int n_in,
                              void* d_out, int out_size) {
    const float* p0 = (const float*)d_in[0];
    const float* p1 = (const float*)d_in[1];
    const float* p2 = (const float*)d_in[2];
    const float* gtb = (const float*)d_in[3];
    const int* gtl = (const int*)d_in[4];
    const float* strides = (const float*)d_in[5];
    float* out = (float*)d_out;

    static cudaStream_t s_side = nullptr;
    static cudaEvent_t ev_fork = nullptr, ev_join = nullptr;
    if (s_side == nullptr) {
        cudaStreamCreateWithFlags(&s_side, cudaStreamNonBlocking);
        cudaEventCreateWithFlags(&ev_fork, cudaEventDisableTiming);
        cudaEventCreateWithFlags(&ev_join, cudaEventDisableTiming);
    }

    // fork: side branch runs the independent 86MB softplus stream
    cudaEventRecord(ev_fork, 0);
    cudaStreamWaitEvent(s_side, ev_fork, 0);
    k_softplus<<<dim3(SP_BLK, BB), 256, 0, s_side>>>(p0, p1, p2);
    cudaEventRecord(ev_join, s_side);

    // main branch: decode -> assign
    k_decode<<<dim3(DEC_BLK, BB), 256>>>(p0, p1, p2, strides);
    k_assign<<<BB * MM, 256>>>(p0, p1, p2, gtb, gtl, strides);

    // join before fg (fg's last block consumes g_sp_part)
    cudaStreamWaitEvent(0, ev_join, 0);
    k_fg<<<FG_BLK, 256>>>(p0, p1, p2, gtb, gtl, strides, out);
}

// round 8
// speedup vs baseline: 1.1454x; 1.0237x over previous
#include <cuda_runtime.h>
#include <cstdint>

#define BB 8
#define MM 32
#define NCLS 80
#define N0 25600
#define N1 6400
#define N2 1600
#define NTOT 33600
#define TOPKK 10
#define DEC_BLK 132          // ceil(33600/256) decode blocks per image
#define SP_BLK 128           // softplus blocks per image
#define S0 512000            // 80*25600/4 float4 per image (p0 cls)
#define S1 128000            // 80*6400/4
#define S2 32000             // 80*1600/4
#define SP_TOT 672000        // S0+S1+S2
#define FG_MAX 2560          // <= 256 GTs * TOPK
#define FG_BLK 320           // 2560 warps / 8 warps-per-block

// ---------------- scratch ----------------
__device__ float4 g_pb[BB * NTOT];                 // decoded pred boxes (image units; in-rect only)
__device__ unsigned long long g_best[BB * NTOT];   // (score_bits<<32 | (0xFFFFFFFF - m)); in-rect only
__device__ double g_sp_part[BB * SP_BLK];          // softplus block partials
__device__ int g_fglist[FG_MAX];                   // compacted fg anchor indices (b*NTOT+n)
__device__ int g_fgtot;
__device__ int g_fgcnt[BB];
__device__ float g_box[BB], g_dfl[BB], g_clspos[BB];
__device__ unsigned int g_done;

// ---------------- helpers ----------------
__device__ __forceinline__ float ciou_f(float b1x1, float b1y1, float b1x2, float b1y2,
                                        float b2x1, float b2y1, float b2x2, float b2y2) {
    const float eps = 1e-7f;
    float w1 = b1x2 - b1x1, h1 = b1y2 - b1y1;
    float w2 = b2x2 - b2x1, h2 = b2y2 - b2y1;
    float iw = fminf(b1x2, b2x2) - fmaxf(b1x1, b2x1);
    float ih = fminf(b1y2, b2y2) - fmaxf(b1y1, b2y1);
    float inter = fmaxf(iw, 0.f) * fmaxf(ih, 0.f);
    float uni = w1 * h1 + w2 * h2 - inter + eps;
    float iou = inter / uni;
    float cw = fmaxf(b1x2, b2x2) - fminf(b1x1, b2x1);
    float ch = fmaxf(b1y2, b2y2) - fminf(b1y1, b2y1);
    float c2 = cw * cw + ch * ch + eps;
    float dx = b2x1 + b2x2 - b1x1 - b1x2;
    float dy = b2y1 + b2y2 - b1y1 - b1y2;
    float rho2 = (dx * dx + dy * dy) * 0.25f;
    float dat = atanf(w2 / (h2 + eps)) - atanf(w1 / (h1 + eps));
    float v = 0.4052847345693511f * dat * dat;
    float alpha = v / (v - iou + (1.f + eps));
    return iou - (rho2 / c2 + v * alpha);
}

__device__ __forceinline__ unsigned long long umax64(unsigned long long a, unsigned long long b) {
    return a > b ? a : b;
}

__device__ __forceinline__ unsigned long long warp_max64(unsigned long long v) {
#pragma unroll
    for (int d = 16; d > 0; d >>= 1)
        v = umax64(v, __shfl_down_sync(0xffffffffu, v, d));
    return v;
}

// ============ k_decode: one thread per anchor, SKIP anchors outside all GT rects ======
__global__ void __launch_bounds__(256) k_decode(
        const float* __restrict__ p0, const float* __restrict__ p1,
        const float* __restrict__ p2, const float* __restrict__ gt_boxes,
        const float* __restrict__ strides) {
    int b = blockIdx.y;
    int tid = threadIdx.x;
    int n = blockIdx.x * 256 + tid;

    __shared__ float4 sgt[MM];
    if (tid < MM) sgt[tid] = ((const float4*)gt_boxes)[b * MM + tid];

    if (blockIdx.x == 0 && tid == 0) {
        g_fgcnt[b] = 0; g_box[b] = 0.f; g_dfl[b] = 0.f; g_clspos[b] = 0.f;
        if (b == 0) { g_done = 0u; g_fgtot = 0; }
    }
    __syncthreads();
    if (n >= NTOT) return;

    const float* p; int HW, q; float st, ax, ay;
    if (n < N0) {
        p = p0; HW = N0; q = n; st = strides[0];
        int qy = q / 160; ax = (float)(q - qy * 160) + 0.5f; ay = (float)qy + 0.5f;
    } else if (n < N0 + N1) {
        p = p1; HW = N1; q = n - N0; st = strides[1];
        int qy = q / 80; ax = (float)(q - qy * 80) + 0.5f; ay = (float)qy + 0.5f;
    } else {
        p = p2; HW = N2; q = n - (N0 + N1); st = strides[2];
        int qy = q / 40; ax = (float)(q - qy * 40) + 0.5f; ay = (float)qy + 0.5f;
    }

    // inclusive in-rect test (identical bounds to k_assign's scan -> strict superset)
    float axi = ax * st, ayi = ay * st;
    bool inside = false;
    for (int m = 0; m < MM; m++) {
        float4 g = sgt[m];
        if (axi >= g.x && axi <= g.z && ayi >= g.y && ayi <= g.w) { inside = true; break; }
    }
    if (!inside) return;   // g_pb / g_best for this anchor are never read

    const float* pb = p + (size_t)b * 144 * HW + q;
    float dist[4];
#pragma unroll
    for (int k = 0; k < 4; k++) {
        float x[16];
#pragma unroll
        for (int r = 0; r < 16; r++) x[r] = pb[(size_t)(k * 16 + r) * HW];
        float se = 0.f, sw = 0.f;
#pragma unroll
        for (int r = 0; r < 16; r++) {
            float e = __expf(x[r]);
            se += e; sw = fmaf(e, (float)r, sw);
        }
        dist[k] = sw / se;
    }
    float4 out;
    out.x = (ax - dist[0]) * st;
    out.y = (ay - dist[1]) * st;
    out.z = (ax + dist[2]) * st;
    out.w = (ay + dist[3]) * st;
    int idx = b * NTOT + n;
    g_pb[idx] = out;
    g_best[idx] = 0xFFFFFFFFull;   // sentinel: score 0, m = 0
}

// ================= k_softplus: independent 86MB stream (side branch) =================
__global__ void __launch_bounds__(256) k_softplus(
        const float* __restrict__ p0, const float* __restrict__ p1,
        const float* __restrict__ p2) {
    int b = blockIdx.y;
    int tid = threadIdx.x;
    const float4* f40 = (const float4*)(p0 + ((size_t)b * 144 + 64) * N0);
    const float4* f41 = (const float4*)(p1 + ((size_t)b * 144 + 64) * N1);
    const float4* f42 = (const float4*)(p2 + ((size_t)b * 144 + 64) * N2);
    float acc = 0.f;
    float P0 = 1.f, P1 = 1.f, P2 = 1.f, P3 = 1.f;
    int cnt = 0;
    for (int i = blockIdx.x * 256 + tid; i < SP_TOT; i += SP_BLK * 256) {
        float4 v;
        if (i < S0)           v = f40[i];
        else if (i < S0 + S1) v = f41[i - S0];
        else                  v = f42[i - S0 - S1];
        acc += fmaxf(v.x, 0.f) + fmaxf(v.y, 0.f) + fmaxf(v.z, 0.f) + fmaxf(v.w, 0.f);
        P0 *= 1.f + __expf(-fabsf(v.x));
        P1 *= 1.f + __expf(-fabsf(v.y));
        P2 *= 1.f + __expf(-fabsf(v.z));
        P3 *= 1.f + __expf(-fabsf(v.w));
        if ((++cnt & 7) == 0) {   // flush every 32 terms (each <= 2)
            acc += __logf((P0 * P1) * (P2 * P3));
            P0 = P1 = P2 = P3 = 1.f;
        }
    }
    acc += __logf((P0 * P1) * (P2 * P3));

    __shared__ double sred[256];
    sred[tid] = (double)acc;
    __syncthreads();
    for (int s = 128; s > 0; s >>= 1) {
        if (tid < s) sred[tid] += sred[tid + s];
        __syncthreads();
    }
    if (tid == 0) g_sp_part[b * SP_BLK + blockIdx.x] = sred[0];
}

// ================= k_assign: one block per (b,m), rect scan + fg compaction =====
__global__ void __launch_bounds__(256) k_assign(
        const float* __restrict__ p0, const float* __restrict__ p1,
        const float* __restrict__ p2,
        const float* __restrict__ gt_boxes, const int* __restrict__ gt_labels,
        const float* __restrict__ strides) {
    __shared__ unsigned long long sh_keys[256 * TOPKK];
    __shared__ unsigned long long sh_w[8];
    __shared__ unsigned long long sh_best;
    __shared__ float sh_fw[8];
    __shared__ float sh_cmax;

    int bm = blockIdx.x;
    int b = bm >> 5, m = bm & 31;
    int tid = threadIdx.x;
    int wid = tid >> 5, lid = tid & 31;

    float gx1 = gt_boxes[(b * MM + m) * 4 + 0];
    float gy1 = gt_boxes[(b * MM + m) * 4 + 1];
    float gx2 = gt_boxes[(b * MM + m) * 4 + 2];
    float gy2 = gt_boxes[(b * MM + m) * 4 + 3];
    int label = gt_labels[b * MM + m];

    float tv[TOPKK]; int tn[TOPKK];
#pragma unroll
    for (int jj = 0; jj < TOPKK; jj++) { tv[jj] = 0.f; tn[jj] = 0x7FFFFFFF; }
    float cmax = 0.f;

#pragma unroll
    for (int lvl = 0; lvl < 3; lvl++) {
        const float* p; int HW, W, noff; float st;
        if (lvl == 0)      { p = p0; HW = N0; W = 160; noff = 0;       st = strides[0]; }
        else if (lvl == 1) { p = p1; HW = N1; W = 80;  noff = N0;      st = strides[1]; }
        else               { p = p2; HW = N2; W = 40;  noff = N0 + N1; st = strides[2]; }

        float inv = 1.f / st;
        int x0 = max(0, (int)(gx1 * inv - 0.5f) - 1);
        int x1 = min(W - 1, (int)(gx2 * inv - 0.5f) + 1);
        int y0 = max(0, (int)(gy1 * inv - 0.5f) - 1);
        int y1 = min(W - 1, (int)(gy2 * inv - 0.5f) + 1);
        int rw = x1 - x0 + 1, rh = y1 - y0 + 1;
        if (rw <= 0 || rh <= 0) continue;
        int tot = rw * rh;
        const float* pcl = p + ((size_t)b * 144 + 64 + label) * HW;

        for (int i = tid; i < tot; i += 256) {
            int qx = x0 + i % rw;
            int qy = y0 + i / rw;
            float ax = ((float)qx + 0.5f) * st;
            float ay = ((float)qy + 0.5f) * st;
            if (ax < gx1 || ax > gx2 || ay < gy1 || ay > gy2) continue;
            int q = qy * W + qx;
            int n = noff + q;
            float4 pbv = g_pb[b * NTOT + n];
            float iou = fmaxf(ciou_f(pbv.x, pbv.y, pbv.z, pbv.w, gx1, gy1, gx2, gy2), 0.f);
            float pcv = pcl[q];
            float ps = 1.f / (1.f + __expf(-pcv));
            float i2 = iou * iou;
            float align = ps * (i2 * i2 * i2);
            cmax = fmaxf(cmax, align);
            if (iou > 0.1f && align > 0.f &&
                ((align > tv[TOPKK - 1]) ||
                 (align == tv[TOPKK - 1] && n < tn[TOPKK - 1]))) {
                float cv = align; int cn = n;
#pragma unroll
                for (int jj = 0; jj < TOPKK; jj++) {
                    bool bt = (cv > tv[jj]) || (cv == tv[jj] && cn < tn[jj]);
                    float nv = bt ? cv : tv[jj];  int nn = bt ? cn : tn[jj];
                    cv = bt ? tv[jj] : cv;        cn = bt ? tn[jj] : cn;
                    tv[jj] = nv;                  tn[jj] = nn;
                }
            }
        }
    }

    // column max (raw align, pre-mask) via warp shuffles
#pragma unroll
    for (int d = 16; d > 0; d >>= 1)
        cmax = fmaxf(cmax, __shfl_down_sync(0xffffffffu, cmax, d));
    if (lid == 0) sh_fw[wid] = cmax;
    __syncthreads();
    if (tid == 0) {
        float c = sh_fw[0];
#pragma unroll
        for (int w = 1; w < 8; w++) c = fmaxf(c, sh_fw[w]);
        sh_cmax = c;
    }

#pragma unroll
    for (int jj = 0; jj < TOPKK; jj++) {
        unsigned long long key = 0ull;
        if (tv[jj] > 0.f)
            key = ((unsigned long long)__float_as_uint(tv[jj]) << 32) |
                  (unsigned long long)(0xFFFFFFFFu - (unsigned)tn[jj]);
        sh_keys[tid * TOPKK + jj] = key;
    }
    __syncthreads();
    float colmax = sh_cmax;

    for (int iter = 0; iter < TOPKK; iter++) {
        unsigned long long loc = 0ull;
#pragma unroll
        for (int jj = 0; jj < TOPKK; jj++)
            loc = umax64(loc, sh_keys[tid + jj * 256]);
        loc = warp_max64(loc);
        if (lid == 0) sh_w[wid] = loc;
        __syncthreads();
        if (tid == 0) {
            unsigned long long v = sh_w[0];
#pragma unroll
            for (int w = 1; w < 8; w++) v = umax64(v, sh_w[w]);
            sh_best = v;
        }
        __syncthreads();
        unsigned long long bestk = sh_best;
        if (bestk == 0ull) break;
#pragma unroll
        for (int jj = 0; jj < TOPKK; jj++)
            if (sh_keys[tid * TOPKK + jj] == bestk) sh_keys[tid * TOPKK + jj] = 0ull;
        if (tid == 0) {
            float val = __uint_as_float((unsigned)(bestk >> 32));
            int n = (int)(0xFFFFFFFFu - (unsigned)(bestk & 0xFFFFFFFFull));
            float norm = val / (colmax + 1e-9f);
            unsigned long long okey =
                ((unsigned long long)__float_as_uint(norm) << 32) |
                (unsigned long long)(0xFFFFFFFFu - (unsigned)m);
            int gidx = b * NTOT + n;
            unsigned long long old = atomicMax(&g_best[gidx], okey);
            // exactly one writer per anchor sees the sentinel -> compaction for free
            if (old == 0xFFFFFFFFull) {
                atomicAdd(&g_fgcnt[b], 1);
                int pos = atomicAdd(&g_fgtot, 1);
                g_fglist[pos] = gidx;
            }
        }
        __syncthreads();
    }
}

// ============ k_fg: one warp per fg anchor + smem atomic aggregation + final ======
__global__ void __launch_bounds__(256) k_fg(
        const float* __restrict__ p0, const float* __restrict__ p1,
        const float* __restrict__ p2,
        const float* __restrict__ gt_boxes, const int* __restrict__ gt_labels,
        const float* __restrict__ strides, float* __restrict__ out) {
    int tid = threadIdx.x;
    int lane = tid & 31;
    int i = blockIdx.x * 8 + (tid >> 5);      // global warp id = fg index

    __shared__ float sbox[BB], sdfl[BB], scls[BB];
    if (tid < BB) { sbox[tid] = 0.f; sdfl[tid] = 0.f; scls[tid] = 0.f; }
    __syncthreads();

    if (i < g_fgtot) {
        int idx = g_fglist[i];
        unsigned long long key = g_best[idx];
        float score = __uint_as_float((unsigned)(key >> 32));
        int b = idx / NTOT, n = idx % NTOT;
        int m = (int)(0xFFFFFFFFu - (unsigned)(key & 0xFFFFFFFFull));

        float gx1 = gt_boxes[(b * MM + m) * 4 + 0];
        float gy1 = gt_boxes[(b * MM + m) * 4 + 1];
        float gx2 = gt_boxes[(b * MM + m) * 4 + 2];
        float gy2 = gt_boxes[(b * MM + m) * 4 + 3];
        int label = gt_labels[b * MM + m];

        const float* p; int HW, W, q; float st;
        if (n < N0)           { p = p0; HW = N0; W = 160; q = n;             st = strides[0]; }
        else if (n < N0 + N1) { p = p1; HW = N1; W = 80;  q = n - N0;        st = strides[1]; }
        else                  { p = p2; HW = N2; W = 40;  q = n - (N0 + N1); st = strides[2]; }
        float ax = (float)(q % W) + 0.5f;
        float ay = (float)(q / W) + 0.5f;

        // lane-parallel load of the 64 dist channels: channel = lane, lane+32
        const float* base = p + (size_t)b * 144 * HW + q;
        float x0 = base[(size_t)lane * HW];          // channels 0-31  (sides 0,1)
        float x1 = base[(size_t)(lane + 32) * HW];   // channels 32-63 (sides 2,3)

        // per-side sum of exp via 16-lane segmented xor-reduction
        float e0 = __expf(x0), e1 = __expf(x1);
#pragma unroll
        for (int d = 1; d < 16; d <<= 1) {
            e0 += __shfl_xor_sync(0xffffffffu, e0, d);
            e1 += __shfl_xor_sync(0xffffffffu, e1, d);
        }
        float lse0 = __logf(__shfl_sync(0xffffffffu, e0, 0));
        float lse1 = __logf(__shfl_sync(0xffffffffu, e0, 16));
        float lse2 = __logf(__shfl_sync(0xffffffffu, e1, 0));
        float lse3 = __logf(__shfl_sync(0xffffffffu, e1, 16));

        // targets (identical on all lanes)
        float t0 = fminf(fmaxf(ax - gx1 / st, 0.f), 14.99f);
        float t1 = fminf(fmaxf(ay - gy1 / st, 0.f), 14.99f);
        float t2 = fminf(fmaxf(gx2 / st - ax, 0.f), 14.99f);
        float t3 = fminf(fmaxf(gy2 / st - ay, 0.f), 14.99f);
        int l0 = (int)t0, l1 = (int)t1, l2 = (int)t2, l3 = (int)t3;
        int r0 = min(l0 + 1, 15), r1 = min(l1 + 1, 15), r2 = min(l2 + 1, 15), r3 = min(l3 + 1, 15);

        float xl0 = __shfl_sync(0xffffffffu, x0, l0);
        float xr0 = __shfl_sync(0xffffffffu, x0, r0);
        float xl1 = __shfl_sync(0xffffffffu, x0, 16 + l1);
        float xr1 = __shfl_sync(0xffffffffu, x0, 16 + r1);
        float xl2 = __shfl_sync(0xffffffffu, x1, l2);
        float xr2 = __shfl_sync(0xffffffffu, x1, r2);
        float xl3 = __shfl_sync(0xffffffffu, x1, 16 + l3);
        float xr3 = __shfl_sync(0xffffffffu, x1, 16 + r3);

        if (lane == 0) {
            float dfl =
                ((float)r0 - t0) * (lse0 - xl0) + (t0 - (float)l0) * (lse0 - xr0) +
                ((float)r1 - t1) * (lse1 - xl1) + (t1 - (float)l1) * (lse1 - xr1) +
                ((float)r2 - t2) * (lse2 - xl2) + (t2 - (float)l2) * (lse2 - xr2) +
                ((float)r3 - t3) * (lse3 - xl3) + (t3 - (float)l3) * (lse3 - xr3);

            float4 pbv = g_pb[idx];
            float boxl = 1.f - ciou_f(pbv.x, pbv.y, pbv.z, pbv.w, gx1, gy1, gx2, gy2);
            float pcv = base[(size_t)(64 + label) * HW];

            atomicAdd(&sbox[b], boxl);
            atomicAdd(&sdfl[b], dfl);
            atomicAdd(&scls[b], pcv * score);
        }
    }
    __syncthreads();
    // push block-aggregated partials (fg entries cluster by b -> ~1 set per block)
    if (tid < BB) {
        if (sbox[tid] != 0.f) atomicAdd(&g_box[tid], sbox[tid]);
        if (sdfl[tid] != 0.f) atomicAdd(&g_dfl[tid], sdfl[tid]);
        if (scls[tid] != 0.f) atomicAdd(&g_clspos[tid], scls[tid]);
    }

    // ---- completion detection: last block computes the final scalar ----
    __shared__ bool s_last;
    __syncthreads();
    if (tid == 0) {
        __threadfence();
        unsigned v = atomicAdd(&g_done, 1u);
        s_last = (v == (unsigned)(gridDim.x - 1));
    }
    __syncthreads();
    if (!s_last) return;

    int w = tid >> 5, l = tid & 31;
    __shared__ double s8[8];
    if (w < 8) {
        double sp = 0.0;
        for (int j = l; j < SP_BLK; j += 32) sp += g_sp_part[w * SP_BLK + j];
#pragma unroll
        for (int d = 16; d > 0; d >>= 1) sp += __shfl_down_sync(0xffffffffu, sp, d);
        if (l == 0) {
            int cnt = g_fgcnt[w];
            double has = cnt > 0 ? 1.0 : 0.0;
            double nf = cnt > 0 ? (double)cnt : 1.0;
            double bl = (double)g_box[w] / nf;
            double dl = (double)g_dfl[w] / (nf * 4.0);
            double cl = (sp - (double)g_clspos[w]) / (double)NTOT;
            s8[w] = (7.5 * bl + 0.5 * cl + 1.5 * dl) * has;
        }
    }
    __syncthreads();
    if (tid == 0) {
        double total = 0.0;
#pragma unroll
        for (int b = 0; b < BB; b++) total += s8[b];
        out[0] = (float)total;
    }
}

// ---------------- launch: fork softplus onto a side branch ----------------
extern "C" void kernel_launch(void* const* d_in, const int* in_sizes, int n_in,
                              void* d_out, int out_size) {
    const float* p0 = (const float*)d_in[0];
    const float* p1 = (const float*)d_in[1];
    const float* p2 = (const float*)d_in[2];
    const float* gtb = (const float*)d_in[3];
    const int* gtl = (const int*)d_in[4];
    const float* strides = (const float*)d_in[5];
    float* out = (float*)d_out;

    static cudaStream_t s_side = nullptr;
    static cudaEvent_t ev_fork = nullptr, ev_join = nullptr;
    if (s_side == nullptr) {
        cudaStreamCreateWithFlags(&s_side, cudaStreamNonBlocking);
        cudaEventCreateWithFlags(&ev_fork, cudaEventDisableTiming);
        cudaEventCreateWithFlags(&ev_join, cudaEventDisableTiming);
    }

    // fork: side branch runs the independent 86MB softplus stream
    cudaEventRecord(ev_fork, 0);
    cudaStreamWaitEvent(s_side, ev_fork, 0);
    k_softplus<<<dim3(SP_BLK, BB), 256, 0, s_side>>>(p0, p1, p2);
    cudaEventRecord(ev_join, s_side);

    // main branch: decode (sparse) -> assign
    k_decode<<<dim3(DEC_BLK, BB), 256>>>(p0, p1, p2, gtb, strides);
    k_assign<<<BB * MM, 256>>>(p0, p1, p2, gtb, gtl, strides);

    // join before fg (fg's last block consumes g_sp_part)
    cudaStreamWaitEvent(0, ev_join, 0);
    k_fg<<<FG_BLK, 256>>>(p0, p1, p2, gtb, gtl, strides, out);
}